// round 3
// baseline (speedup 1.0000x reference)
#include <cuda_runtime.h>
#include <cstdint>

#define Nn 50000
#define Ee 800000
#define Hh 256
#define NLAYERS 3
#define MP 68     // Xs row stride (floats): 16B-aligned, 4-way write conflicts only
#define KT 32     // K tile

// ---------------- scratch (no allocs allowed -> device globals) ----------------
static __device__ float g_h  [(size_t)Nn*Hh];
static __device__ float g_P  [(size_t)Nn*Hh];
static __device__ float g_Q  [(size_t)Nn*Hh];
static __device__ float g_agg[(size_t)Nn*Hh];
static __device__ float g_U  [(size_t)Nn*Hh];
// LUT layout (units of 256 floats): REL(0..7) RSRC(8..15) RDST(16..23)
// CSRC(24..26) CDST(27..29) NROLE(30..37) NCOL(38..40)
static __device__ float g_lut[41*Hh];

#define LUT_REL  0
#define LUT_RS   (8*Hh)
#define LUT_RD   (16*Hh)
#define LUT_CS   (24*Hh)
#define LUT_CD   (27*Hh)
#define LUT_NR   (30*Hh)
#define LUT_NC   (38*Hh)

__device__ __forceinline__ float silu_f(float x) {
    return __fdividef(x, 1.0f + __expf(-x));
}

__device__ __forceinline__ void red_add_v4(float* p, float4 v) {
    asm volatile("red.global.add.v4.f32 [%0], {%1,%2,%3,%4};"
                 :: "l"(p), "f"(v.x), "f"(v.y), "f"(v.z), "f"(v.w) : "memory");
}

// ---------------- zero g_agg (replaces cudaMemsetAsync for capture safety) ----
__global__ void k_zero() {
    size_t i = (size_t)blockIdx.x * blockDim.x + threadIdx.x;
    float4* p = (float4*)g_agg;
    if (i < (size_t)Nn*Hh/4) p[i] = make_float4(0.f,0.f,0.f,0.f);
}

// Transpose-copy 64 rows (clamped) of a [*,256] matrix into Xs[k][m]
__device__ __forceinline__ void build_rows(const float* __restrict__ src, int row0,
                                           float* __restrict__ Xs) {
    int k = threadIdx.x;
    #pragma unroll 4
    for (int m = 0; m < 64; m++) {
        int r = row0 + m; if (r > Nn - 1) r = Nn - 1;
        Xs[k*MP + m] = src[(size_t)r*Hh + k];
    }
}

// Register-tiled GEMM: 64 rows x 256 cols, K=256.
// Thread tile: 16 rows (mgrp=tid>>6) x 4 cols (nthr=tid&63).
// t-operands come from smem as warp-broadcast LDS.128 -> 64 FMA per 5 LDS.
__device__ __forceinline__ void gemm_core(const float* __restrict__ W,
                                          float* __restrict__ Xs,
                                          float* __restrict__ Ws,
                                          float4 (&acc)[16]) {
    int tid = threadIdx.x;
    int nthr = tid & 63, mgrp = tid >> 6;
    const float4* Wg4 = (const float4*)W;
    float4* Ws4 = (float4*)Ws;
    for (int kt = 0; kt < Hh/KT; kt++) {
        __syncthreads();
        #pragma unroll
        for (int i = 0; i < (KT*64)/256; i++) {
            int idx = i*256 + tid;
            Ws4[idx] = Wg4[kt*(KT*64) + idx];
        }
        __syncthreads();
        #pragma unroll
        for (int kk = 0; kk < KT; kk++) {
            int k = kt*KT + kk;
            float4 w = Ws4[kk*64 + nthr];
            const float4* xp = (const float4*)(Xs + k*MP + mgrp*16);
            #pragma unroll
            for (int j = 0; j < 4; j++) {
                float4 tq = xp[j];
                float tv[4] = {tq.x, tq.y, tq.z, tq.w};
                #pragma unroll
                for (int i2 = 0; i2 < 4; i2++) {
                    float t = tv[i2];
                    float4& a = acc[j*4 + i2];
                    a.x += t*w.x; a.y += t*w.y; a.z += t*w.z; a.w += t*w.w;
                }
            }
        }
    }
}

// ---------------- input projection: h = [scalars|col_emb|role_emb] @ in_w + in_b
__global__ void k_input(const float* __restrict__ scalars,
                        const int* __restrict__ colr, const int* __restrict__ role,
                        const float* __restrict__ cemb, const float* __restrict__ remb,
                        const float* __restrict__ in_w, const float* __restrict__ in_b) {
    int node0 = blockIdx.x * 64;
    int n = threadIdx.x;
    for (int mi = 0; mi < 64; mi++) {
        int node = node0 + mi;
        if (node >= Nn) return;
        float acc = in_b[n];
        const float* s = scalars + (size_t)node*16;
        #pragma unroll
        for (int k = 0; k < 16; k++) acc += s[k]*in_w[k*Hh + n];
        const float* ce = cemb + colr[node]*8;
        #pragma unroll
        for (int k = 0; k < 8; k++) acc += ce[k]*in_w[(16+k)*Hh + n];
        const float* re = remb + role[node]*8;
        #pragma unroll
        for (int k = 0; k < 8; k++) acc += re[k]*in_w[(24+k)*Hh + n];
        g_h[(size_t)node*Hh + n] = acc;
    }
}

// ---------------- per-layer LUT vectors (categorical rows folded to 256-vectors)
__global__ void k_lut(const float* __restrict__ rel_embs, const float* __restrict__ role_embs,
                      const float* __restrict__ col_embs,
                      const float* __restrict__ e1w, const float* __restrict__ e1b,
                      const float* __restrict__ n1w, const float* __restrict__ n1b, int li) {
    int n = threadIdx.x;
    int b = blockIdx.x;
    const float* e1wl = e1w + (size_t)li*560*Hh;
    const float* n1wl = n1w + (size_t)li*528*Hh;
    float acc = 0.f; const float* emb; const float* W; int kd;
    if (b < 8)       { emb = rel_embs  + (li*8 + b)     *16; W = e1wl + 512*Hh; kd = 16; acc = e1b[li*Hh + n]; }
    else if (b < 16) { emb = role_embs + (li*8 + (b-8)) *8;  W = e1wl + 528*Hh; kd = 8; }
    else if (b < 24) { emb = role_embs + (li*8 + (b-16))*8;  W = e1wl + 536*Hh; kd = 8; }
    else if (b < 27) { emb = col_embs  + (li*3 + (b-24))*8;  W = e1wl + 544*Hh; kd = 8; }
    else if (b < 30) { emb = col_embs  + (li*3 + (b-27))*8;  W = e1wl + 552*Hh; kd = 8; }
    else if (b < 38) { emb = role_embs + (li*8 + (b-30))*8;  W = n1wl + 512*Hh; kd = 8; acc = n1b[li*Hh + n]; }
    else             { emb = col_embs  + (li*3 + (b-38))*8;  W = n1wl + 520*Hh; kd = 8; }
    for (int k = 0; k < kd; k++) acc += emb[k]*W[k*Hh + n];
    g_lut[b*Hh + n] = acc;
}

// ---------------- P/Q node GEMMs (gridDim.y: 0 -> P (W_src), 1 -> Q (W_dst))
__global__ void __launch_bounds__(256,2)
k_pq(const float* __restrict__ e1w, const int* __restrict__ role,
     const int* __restrict__ colr, int li) {
    extern __shared__ float sm[];
    float* Xs = sm;
    float* Ws = sm + 256*MP;
    __shared__ int rs[64], cs[64];
    int tid = threadIdx.x;
    int row0 = blockIdx.x * 64;
    bool isQ = (blockIdx.y == 1);
    if (tid < 64) {
        int r = row0 + tid; if (r > Nn-1) r = Nn-1;
        rs[tid] = role[r]; cs[tid] = colr[r];
    }
    build_rows(g_h, row0, Xs);
    float4 acc[16];
    #pragma unroll
    for (int i = 0; i < 16; i++) acc[i] = make_float4(0.f,0.f,0.f,0.f);
    const float* W = e1w + (size_t)li*560*Hh + (isQ ? (size_t)256*Hh : 0);
    gemm_core(W, Xs, Ws, acc);
    int nthr = tid & 63, mgrp = tid >> 6, n0 = nthr*4;
    float* out = isQ ? g_Q : g_P;
    const float* lutR = g_lut + (isQ ? LUT_RD : LUT_RS);
    const float* lutC = g_lut + (isQ ? LUT_CD : LUT_CS);
    #pragma unroll
    for (int mi = 0; mi < 16; mi++) {
        int m = mgrp*16 + mi; int node = row0 + m;
        if (node >= Nn) break;
        float4 lr = *(const float4*)(lutR + rs[m]*Hh + n0);
        float4 lc = *(const float4*)(lutC + cs[m]*Hh + n0);
        float4 v = acc[mi];
        v.x += lr.x + lc.x; v.y += lr.y + lc.y; v.z += lr.z + lc.z; v.w += lr.w + lc.w;
        *(float4*)(out + (size_t)node*Hh + n0) = v;
    }
}

// ---------------- fused edge kernel: t=silu(P[src]+Q[dst]+rel_lut); m=silu(t@e2w+b); agg[dst]+=m
__global__ void __launch_bounds__(256,2)
k_edge(const int* __restrict__ src, const int* __restrict__ dst, const int* __restrict__ rel,
       const float* __restrict__ e2w, const float* __restrict__ e2b, int li) {
    extern __shared__ float sm[];
    float* Xs = sm;
    float* Ws = sm + 256*MP;
    __shared__ int ss[64], ds[64], rr[64];
    int tid = threadIdx.x;
    int e0 = blockIdx.x * 64;
    if (tid < 64) { ss[tid] = src[e0+tid]; ds[tid] = dst[e0+tid]; rr[tid] = rel[e0+tid]; }
    __syncthreads();
    int k = tid;
    #pragma unroll 4
    for (int m = 0; m < 64; m++) {
        float v = g_P[(size_t)ss[m]*Hh + k] + g_Q[(size_t)ds[m]*Hh + k]
                + g_lut[LUT_REL + rr[m]*Hh + k];
        Xs[k*MP + m] = silu_f(v);
    }
    float4 acc[16];
    #pragma unroll
    for (int i = 0; i < 16; i++) acc[i] = make_float4(0.f,0.f,0.f,0.f);
    gemm_core(e2w + (size_t)li*Hh*Hh, Xs, Ws, acc);
    int nthr = tid & 63, mgrp = tid >> 6, n0 = nthr*4;
    float4 bb = *(const float4*)(e2b + li*Hh + n0);
    #pragma unroll
    for (int mi = 0; mi < 16; mi++) {
        int m = mgrp*16 + mi;
        float4 v = acc[mi];
        v.x = silu_f(v.x + bb.x); v.y = silu_f(v.y + bb.y);
        v.z = silu_f(v.z + bb.z); v.w = silu_f(v.w + bb.w);
        red_add_v4(&g_agg[(size_t)ds[m]*Hh + n0], v);
    }
}

// ---------------- node MLP first linear: U = silu(h@Wh + agg@Wagg + role_lut + col_lut)
__global__ void __launch_bounds__(256,2)
k_n1(const float* __restrict__ n1w, const int* __restrict__ role,
     const int* __restrict__ colr, int li) {
    extern __shared__ float sm[];
    float* Xs = sm;
    float* Ws = sm + 256*MP;
    __shared__ int rs[64], cs[64];
    int tid = threadIdx.x;
    int row0 = blockIdx.x * 64;
    if (tid < 64) {
        int r = row0 + tid; if (r > Nn-1) r = Nn-1;
        rs[tid] = role[r]; cs[tid] = colr[r];
    }
    build_rows(g_h, row0, Xs);
    float4 acc[16];
    #pragma unroll
    for (int i = 0; i < 16; i++) acc[i] = make_float4(0.f,0.f,0.f,0.f);
    const float* Wl = n1w + (size_t)li*528*Hh;
    gemm_core(Wl, Xs, Ws, acc);                    // rows 0..255 (h)
    __syncthreads();
    build_rows(g_agg, row0, Xs);
    gemm_core(Wl + (size_t)256*Hh, Xs, Ws, acc);   // rows 256..511 (agg)
    int nthr = tid & 63, mgrp = tid >> 6, n0 = nthr*4;
    #pragma unroll
    for (int mi = 0; mi < 16; mi++) {
        int m = mgrp*16 + mi; int node = row0 + m;
        if (node >= Nn) break;
        float4 lr = *(const float4*)(g_lut + LUT_NR + rs[m]*Hh + n0);
        float4 lc = *(const float4*)(g_lut + LUT_NC + cs[m]*Hh + n0);
        float4 v = acc[mi];
        v.x = silu_f(v.x + lr.x + lc.x); v.y = silu_f(v.y + lr.y + lc.y);
        v.z = silu_f(v.z + lr.z + lc.z); v.w = silu_f(v.w + lr.w + lc.w);
        *(float4*)(g_U + (size_t)node*Hh + n0) = v;
    }
}

// ---------------- node MLP second linear + residual + LayerNorm -> writes g_h
__global__ void __launch_bounds__(256,2)
k_n2(const float* __restrict__ n2w, const float* __restrict__ n2b,
     const float* __restrict__ lng, const float* __restrict__ lnb, int li) {
    extern __shared__ float sm[];
    float* Xs = sm;
    float* Ws = sm + 256*MP;
    __shared__ float mus[64], rss[64];
    int tid = threadIdx.x;
    int row0 = blockIdx.x * 64;
    build_rows(g_U, row0, Xs);
    float4 acc[16];
    #pragma unroll
    for (int i = 0; i < 16; i++) acc[i] = make_float4(0.f,0.f,0.f,0.f);
    gemm_core(n2w + (size_t)li*Hh*Hh, Xs, Ws, acc);
    __syncthreads();                         // done reading Xs: reuse as x buffer
    float* xs = sm;                          // [64][260]
    int nthr = tid & 63, mgrp = tid >> 6, n0 = nthr*4;
    float4 bb = *(const float4*)(n2b + li*Hh + n0);
    #pragma unroll
    for (int mi = 0; mi < 16; mi++) {
        int m = mgrp*16 + mi; int node = row0 + m; int nc = (node > Nn-1) ? Nn-1 : node;
        float4 hv = *(const float4*)(g_h + (size_t)nc*Hh + n0);
        float4 v = acc[mi];
        v.x += bb.x + hv.x; v.y += bb.y + hv.y; v.z += bb.z + hv.z; v.w += bb.w + hv.w;
        *(float4*)(xs + m*260 + n0) = v;
    }
    __syncthreads();
    int lane = tid & 31, w = tid >> 5;
    for (int rrow = w*8; rrow < w*8 + 8; rrow++) {
        float s = 0.f, q = 0.f;
        #pragma unroll
        for (int j = 0; j < 8; j++) {
            float v = xs[rrow*260 + lane + j*32];
            s += v; q += v*v;
        }
        #pragma unroll
        for (int o = 16; o; o >>= 1) {
            s += __shfl_xor_sync(0xffffffffu, s, o);
            q += __shfl_xor_sync(0xffffffffu, q, o);
        }
        if (lane == 0) {
            float mu = s * (1.f/256.f);
            float var = q * (1.f/256.f) - mu*mu;
            mus[rrow] = mu;
            rss[rrow] = rsqrtf(fmaxf(var, 0.f) + 1e-5f);
        }
    }
    __syncthreads();
    for (int idx = tid; idx < 64*Hh; idx += 256) {
        int m = idx >> 8, n = idx & 255;
        int node = row0 + m;
        if (node < Nn) {
            float v = (xs[m*260 + n] - mus[m]) * rss[m] * lng[li*Hh + n] + lnb[li*Hh + n];
            g_h[(size_t)node*Hh + n] = v;
        }
    }
}

// ---------------- output projection: out = h @ out_w[256,64] + out_b
__global__ void __launch_bounds__(256,2)
k_out(const float* __restrict__ outw, const float* __restrict__ outb, float* __restrict__ out) {
    extern __shared__ float sm[];
    float* Xs = sm;
    float* Ws = sm + 256*MP;   // [KT][64]
    int tid = threadIdx.x;
    int row0 = blockIdx.x * 64;
    build_rows(g_h, row0, Xs);
    int nthr = tid & 15, mgrp = tid >> 4, n0 = nthr*4;
    float4 acc[4];
    #pragma unroll
    for (int i = 0; i < 4; i++) acc[i] = make_float4(0.f,0.f,0.f,0.f);
    const float4* Wg4 = (const float4*)outw;
    float4* Ws4 = (float4*)Ws;
    for (int kt = 0; kt < 8; kt++) {
        __syncthreads();
        Ws4[tid]       = Wg4[kt*512 + tid];
        Ws4[256 + tid] = Wg4[kt*512 + 256 + tid];
        __syncthreads();
        #pragma unroll
        for (int kk = 0; kk < KT; kk++) {
            int k = kt*KT + kk;
            float4 w = Ws4[kk*16 + nthr];
            float4 t = *(const float4*)(Xs + k*MP + mgrp*4);
            acc[0].x += t.x*w.x; acc[0].y += t.x*w.y; acc[0].z += t.x*w.z; acc[0].w += t.x*w.w;
            acc[1].x += t.y*w.x; acc[1].y += t.y*w.y; acc[1].z += t.y*w.z; acc[1].w += t.y*w.w;
            acc[2].x += t.z*w.x; acc[2].y += t.z*w.y; acc[2].z += t.z*w.z; acc[2].w += t.z*w.w;
            acc[3].x += t.w*w.x; acc[3].y += t.w*w.y; acc[3].z += t.w*w.z; acc[3].w += t.w*w.w;
        }
    }
    float4 bb = *(const float4*)(outb + n0);
    #pragma unroll
    for (int i = 0; i < 4; i++) {
        int node = row0 + mgrp*4 + i;
        if (node < Nn) {
            float4 v = acc[i];
            v.x += bb.x; v.y += bb.y; v.z += bb.z; v.w += bb.w;
            *(float4*)(out + (size_t)node*64 + n0) = v;
        }
    }
}

// ---------------- launcher ----------------
extern "C" void kernel_launch(void* const* d_in, const int* in_sizes, int n_in,
                              void* d_out, int out_size) {
    const float* scalars      = (const float*)d_in[0];
    const int*   eidx         = (const int*)  d_in[1];
    const int*   erel         = (const int*)  d_in[2];
    const int*   ncol         = (const int*)  d_in[3];
    const int*   nrole        = (const int*)  d_in[4];
    const float* blk_role_emb = (const float*)d_in[5];
    const float* blk_col_emb  = (const float*)d_in[6];
    const float* in_w         = (const float*)d_in[7];
    const float* in_b         = (const float*)d_in[8];
    const float* rel_embs     = (const float*)d_in[9];
    const float* role_embs    = (const float*)d_in[10];
    const float* col_embs     = (const float*)d_in[11];
    const float* e1_w         = (const float*)d_in[12];
    const float* e1_b         = (const float*)d_in[13];
    const float* e2_w         = (const float*)d_in[14];
    const float* e2_b         = (const float*)d_in[15];
    const float* n1_w         = (const float*)d_in[16];
    const float* n1_b         = (const float*)d_in[17];
    const float* n2_w         = (const float*)d_in[18];
    const float* n2_b         = (const float*)d_in[19];
    const float* ln_g         = (const float*)d_in[20];
    const float* ln_b         = (const float*)d_in[21];
    const float* out_w        = (const float*)d_in[22];
    const float* out_b        = (const float*)d_in[23];
    const int* esrc = eidx;
    const int* edst = eidx + Ee;

    size_t sm_gemm = (size_t)(256*MP + KT*256) * sizeof(float);  // 102400 B
    size_t sm_out  = (size_t)(256*MP + KT*64)  * sizeof(float);  // 77824 B
    cudaFuncSetAttribute(k_pq,   cudaFuncAttributeMaxDynamicSharedMemorySize, (int)sm_gemm);
    cudaFuncSetAttribute(k_edge, cudaFuncAttributeMaxDynamicSharedMemorySize, (int)sm_gemm);
    cudaFuncSetAttribute(k_n1,   cudaFuncAttributeMaxDynamicSharedMemorySize, (int)sm_gemm);
    cudaFuncSetAttribute(k_n2,   cudaFuncAttributeMaxDynamicSharedMemorySize, (int)sm_gemm);
    cudaFuncSetAttribute(k_out,  cudaFuncAttributeMaxDynamicSharedMemorySize, (int)sm_out);

    int nb = (Nn + 63) / 64;  // 782
    int zb = (int)(((size_t)Nn*Hh/4 + 255) / 256);

    k_input<<<nb, 256>>>(scalars, ncol, nrole, blk_col_emb, blk_role_emb, in_w, in_b);

    for (int li = 0; li < NLAYERS; li++) {
        k_lut<<<41, 256>>>(rel_embs, role_embs, col_embs, e1_w, e1_b, n1_w, n1_b, li);
        dim3 gpq(nb, 2);
        k_pq<<<gpq, 256, sm_gemm>>>(e1_w, nrole, ncol, li);
        k_zero<<<zb, 256>>>();
        k_edge<<<Ee/64, 256, sm_gemm>>>(esrc, edst, erel, e2_w, e2_b, li);
        k_n1<<<nb, 256, sm_gemm>>>(n1_w, nrole, ncol, li);
        k_n2<<<nb, 256, sm_gemm>>>(n2_w, n2_b, ln_g, ln_b, li);
    }
    k_out<<<nb, 256, sm_out>>>(out_w, out_b, (float*)d_out);
}

// round 4
// speedup vs baseline: 1.0684x; 1.0684x over previous
#include <cuda_runtime.h>
#include <cstdint>

#define Nn 50000
#define Ee 800000
#define Hh 256
#define NLAYERS 3
#define MP 68     // Xs row stride (floats): 16B-aligned
#define KT 32     // K tile

// ---------------- scratch (no allocs allowed -> device globals) ----------------
static __device__ float g_h  [(size_t)Nn*Hh];
static __device__ float g_P  [(size_t)Nn*Hh];
static __device__ float g_Q  [(size_t)Nn*Hh];
static __device__ float g_agg[(size_t)Nn*Hh];
static __device__ float g_U  [(size_t)Nn*Hh];
// LUT layout (units of 256 floats): REL(0..7) RSRC(8..15) RDST(16..23)
// CSRC(24..26) CDST(27..29) NROLE(30..37) NCOL(38..40)
static __device__ float g_lut[41*Hh];

#define LUT_REL  0
#define LUT_RS   (8*Hh)
#define LUT_RD   (16*Hh)
#define LUT_CS   (24*Hh)
#define LUT_CD   (27*Hh)
#define LUT_NR   (30*Hh)
#define LUT_NC   (38*Hh)

__device__ __forceinline__ float silu_f(float x) {
    return __fdividef(x, 1.0f + __expf(-x));
}

__device__ __forceinline__ void red_add_v4(float* p, float4 v) {
    asm volatile("red.global.add.v4.f32 [%0], {%1,%2,%3,%4};"
                 :: "l"(p), "f"(v.x), "f"(v.y), "f"(v.z), "f"(v.w) : "memory");
}

// packed f32x2 helpers (FFMA2 path — 2 FMAs per issue slot)
__device__ __forceinline__ unsigned long long dup2(float x) {
    unsigned long long r;
    asm("mov.b64 %0, {%1,%1};" : "=l"(r) : "f"(x));
    return r;
}
__device__ __forceinline__ void fma2(unsigned long long& a, unsigned long long t,
                                     unsigned long long w) {
    asm("fma.rn.f32x2 %0, %1, %2, %0;" : "+l"(a) : "l"(t), "l"(w));
}
__device__ __forceinline__ void unpack2(unsigned long long u, float& a, float& b) {
    asm("mov.b64 {%0,%1}, %2;" : "=f"(a), "=f"(b) : "l"(u));
}

// ---------------- zero g_agg (graph-capture-safe memset) ----
__global__ void k_zero() {
    size_t i = (size_t)blockIdx.x * blockDim.x + threadIdx.x;
    float4* p = (float4*)g_agg;
    if (i < (size_t)Nn*Hh/4) p[i] = make_float4(0.f,0.f,0.f,0.f);
}

// Transpose-copy 64 rows (clamped) of a [*,256] matrix into Xs[k][m]
__device__ __forceinline__ void build_rows(const float* __restrict__ src, int row0,
                                           float* __restrict__ Xs) {
    int k = threadIdx.x;
    #pragma unroll 4
    for (int m = 0; m < 64; m++) {
        int r = row0 + m; if (r > Nn - 1) r = Nn - 1;
        Xs[k*MP + m] = src[(size_t)r*Hh + k];
    }
}

// Register-tiled GEMM: 64 rows x 256 cols, K=256, packed-f32x2 accumulators.
// Thread tile: 16 rows (mgrp=tid>>6) x 4 cols (nthr=tid&63).
// acc[p*4+n] holds rows (mgrp*16+2p, +2p+1) at col nthr*4+n as one f32x2.
// Inner loop per k: 32 FFMA2 + 4 dup-MOV + 5 LDS.128.
__device__ __forceinline__ void gemm_core(const float* __restrict__ W,
                                          float* __restrict__ Xs,
                                          float* __restrict__ Ws,
                                          unsigned long long (&acc)[32]) {
    int tid = threadIdx.x;
    int nthr = tid & 63, mgrp = tid >> 6;
    const float4* Wg4 = (const float4*)W;
    float4* Ws4 = (float4*)Ws;
    for (int kt = 0; kt < Hh/KT; kt++) {
        __syncthreads();
        #pragma unroll
        for (int i = 0; i < (KT*64)/256; i++) {
            int idx = i*256 + tid;
            Ws4[idx] = Wg4[kt*(KT*64) + idx];
        }
        __syncthreads();
        #pragma unroll
        for (int kk = 0; kk < KT; kk++) {
            int k = kt*KT + kk;
            float4 w = Ws4[kk*64 + nthr];
            unsigned long long wd0 = dup2(w.x), wd1 = dup2(w.y),
                               wd2 = dup2(w.z), wd3 = dup2(w.w);
            const ulonglong2* xp = (const ulonglong2*)(Xs + k*MP + mgrp*16);
            #pragma unroll
            for (int j = 0; j < 4; j++) {
                ulonglong2 tp = xp[j];   // rows pair 2j (lo) and 2j+1 (hi)
                fma2(acc[(2*j)*4+0],   tp.x, wd0);
                fma2(acc[(2*j)*4+1],   tp.x, wd1);
                fma2(acc[(2*j)*4+2],   tp.x, wd2);
                fma2(acc[(2*j)*4+3],   tp.x, wd3);
                fma2(acc[(2*j+1)*4+0], tp.y, wd0);
                fma2(acc[(2*j+1)*4+1], tp.y, wd1);
                fma2(acc[(2*j+1)*4+2], tp.y, wd2);
                fma2(acc[(2*j+1)*4+3], tp.y, wd3);
            }
        }
    }
}

// Unpack one m-pair (p) into two float4 row vectors
__device__ __forceinline__ void unpack_pair(const unsigned long long (&acc)[32], int p,
                                            float4& v0, float4& v1) {
    unpack2(acc[p*4+0], v0.x, v1.x);
    unpack2(acc[p*4+1], v0.y, v1.y);
    unpack2(acc[p*4+2], v0.z, v1.z);
    unpack2(acc[p*4+3], v0.w, v1.w);
}

// ---------------- input projection: h = [scalars|col_emb|role_emb] @ in_w + in_b
__global__ void k_input(const float* __restrict__ scalars,
                        const int* __restrict__ colr, const int* __restrict__ role,
                        const float* __restrict__ cemb, const float* __restrict__ remb,
                        const float* __restrict__ in_w, const float* __restrict__ in_b) {
    int node0 = blockIdx.x * 64;
    int n = threadIdx.x;
    for (int mi = 0; mi < 64; mi++) {
        int node = node0 + mi;
        if (node >= Nn) return;
        float acc = in_b[n];
        const float* s = scalars + (size_t)node*16;
        #pragma unroll
        for (int k = 0; k < 16; k++) acc += s[k]*in_w[k*Hh + n];
        const float* ce = cemb + colr[node]*8;
        #pragma unroll
        for (int k = 0; k < 8; k++) acc += ce[k]*in_w[(16+k)*Hh + n];
        const float* re = remb + role[node]*8;
        #pragma unroll
        for (int k = 0; k < 8; k++) acc += re[k]*in_w[(24+k)*Hh + n];
        g_h[(size_t)node*Hh + n] = acc;
    }
}

// ---------------- per-layer LUT vectors (categorical rows folded to 256-vectors)
__global__ void k_lut(const float* __restrict__ rel_embs, const float* __restrict__ role_embs,
                      const float* __restrict__ col_embs,
                      const float* __restrict__ e1w, const float* __restrict__ e1b,
                      const float* __restrict__ n1w, const float* __restrict__ n1b, int li) {
    int n = threadIdx.x;
    int b = blockIdx.x;
    const float* e1wl = e1w + (size_t)li*560*Hh;
    const float* n1wl = n1w + (size_t)li*528*Hh;
    float acc = 0.f; const float* emb; const float* W; int kd;
    if (b < 8)       { emb = rel_embs  + (li*8 + b)     *16; W = e1wl + 512*Hh; kd = 16; acc = e1b[li*Hh + n]; }
    else if (b < 16) { emb = role_embs + (li*8 + (b-8)) *8;  W = e1wl + 528*Hh; kd = 8; }
    else if (b < 24) { emb = role_embs + (li*8 + (b-16))*8;  W = e1wl + 536*Hh; kd = 8; }
    else if (b < 27) { emb = col_embs  + (li*3 + (b-24))*8;  W = e1wl + 544*Hh; kd = 8; }
    else if (b < 30) { emb = col_embs  + (li*3 + (b-27))*8;  W = e1wl + 552*Hh; kd = 8; }
    else if (b < 38) { emb = role_embs + (li*8 + (b-30))*8;  W = n1wl + 512*Hh; kd = 8; acc = n1b[li*Hh + n]; }
    else             { emb = col_embs  + (li*3 + (b-38))*8;  W = n1wl + 520*Hh; kd = 8; }
    for (int k = 0; k < kd; k++) acc += emb[k]*W[k*Hh + n];
    g_lut[b*Hh + n] = acc;
}

// ---------------- P/Q node GEMMs (gridDim.y: 0 -> P (W_src), 1 -> Q (W_dst))
__global__ void __launch_bounds__(256,2)
k_pq(const float* __restrict__ e1w, const int* __restrict__ role,
     const int* __restrict__ colr, int li) {
    extern __shared__ float sm[];
    float* Xs = sm;
    float* Ws = sm + 256*MP;
    __shared__ int rs[64], cs[64];
    int tid = threadIdx.x;
    int row0 = blockIdx.x * 64;
    bool isQ = (blockIdx.y == 1);
    if (tid < 64) {
        int r = row0 + tid; if (r > Nn-1) r = Nn-1;
        rs[tid] = role[r]; cs[tid] = colr[r];
    }
    build_rows(g_h, row0, Xs);
    unsigned long long acc[32];
    #pragma unroll
    for (int i = 0; i < 32; i++) acc[i] = 0ull;
    const float* W = e1w + (size_t)li*560*Hh + (isQ ? (size_t)256*Hh : 0);
    gemm_core(W, Xs, Ws, acc);
    int nthr = tid & 63, mgrp = tid >> 6, n0 = nthr*4;
    float* out = isQ ? g_Q : g_P;
    const float* lutR = g_lut + (isQ ? LUT_RD : LUT_RS);
    const float* lutC = g_lut + (isQ ? LUT_CD : LUT_CS);
    #pragma unroll
    for (int p = 0; p < 8; p++) {
        float4 vv[2];
        unpack_pair(acc, p, vv[0], vv[1]);
        #pragma unroll
        for (int h = 0; h < 2; h++) {
            int m = mgrp*16 + 2*p + h; int node = row0 + m;
            if (node >= Nn) continue;
            float4 lr = *(const float4*)(lutR + rs[m]*Hh + n0);
            float4 lc = *(const float4*)(lutC + cs[m]*Hh + n0);
            float4 v = vv[h];
            v.x += lr.x + lc.x; v.y += lr.y + lc.y; v.z += lr.z + lc.z; v.w += lr.w + lc.w;
            *(float4*)(out + (size_t)node*Hh + n0) = v;
        }
    }
}

// ---------------- fused edge kernel: t=silu(P[src]+Q[dst]+rel_lut); m=silu(t@e2w+b); agg[dst]+=m
__global__ void __launch_bounds__(256,2)
k_edge(const int* __restrict__ src, const int* __restrict__ dst, const int* __restrict__ rel,
       const float* __restrict__ e2w, const float* __restrict__ e2b, int li) {
    extern __shared__ float sm[];
    float* Xs = sm;
    float* Ws = sm + 256*MP;
    __shared__ int ss[64], ds[64], rr[64];
    int tid = threadIdx.x;
    int e0 = blockIdx.x * 64;
    if (tid < 64) { ss[tid] = src[e0+tid]; ds[tid] = dst[e0+tid]; rr[tid] = rel[e0+tid]; }
    __syncthreads();
    int k = tid;
    #pragma unroll 4
    for (int m = 0; m < 64; m++) {
        float v = g_P[(size_t)ss[m]*Hh + k] + g_Q[(size_t)ds[m]*Hh + k]
                + g_lut[LUT_REL + rr[m]*Hh + k];
        Xs[k*MP + m] = silu_f(v);
    }
    unsigned long long acc[32];
    #pragma unroll
    for (int i = 0; i < 32; i++) acc[i] = 0ull;
    gemm_core(e2w + (size_t)li*Hh*Hh, Xs, Ws, acc);
    int nthr = tid & 63, mgrp = tid >> 6, n0 = nthr*4;
    float4 bb = *(const float4*)(e2b + li*Hh + n0);
    #pragma unroll
    for (int p = 0; p < 8; p++) {
        float4 vv[2];
        unpack_pair(acc, p, vv[0], vv[1]);
        #pragma unroll
        for (int h = 0; h < 2; h++) {
            int m = mgrp*16 + 2*p + h;
            float4 v = vv[h];
            v.x = silu_f(v.x + bb.x); v.y = silu_f(v.y + bb.y);
            v.z = silu_f(v.z + bb.z); v.w = silu_f(v.w + bb.w);
            red_add_v4(&g_agg[(size_t)ds[m]*Hh + n0], v);
        }
    }
}

// ---------------- node MLP first linear: U = silu(h@Wh + agg@Wagg + role_lut + col_lut)
__global__ void __launch_bounds__(256,2)
k_n1(const float* __restrict__ n1w, const int* __restrict__ role,
     const int* __restrict__ colr, int li) {
    extern __shared__ float sm[];
    float* Xs = sm;
    float* Ws = sm + 256*MP;
    __shared__ int rs[64], cs[64];
    int tid = threadIdx.x;
    int row0 = blockIdx.x * 64;
    if (tid < 64) {
        int r = row0 + tid; if (r > Nn-1) r = Nn-1;
        rs[tid] = role[r]; cs[tid] = colr[r];
    }
    build_rows(g_h, row0, Xs);
    unsigned long long acc[32];
    #pragma unroll
    for (int i = 0; i < 32; i++) acc[i] = 0ull;
    const float* Wl = n1w + (size_t)li*528*Hh;
    gemm_core(Wl, Xs, Ws, acc);                    // rows 0..255 (h)
    __syncthreads();
    build_rows(g_agg, row0, Xs);
    gemm_core(Wl + (size_t)256*Hh, Xs, Ws, acc);   // rows 256..511 (agg)
    int nthr = tid & 63, mgrp = tid >> 6, n0 = nthr*4;
    #pragma unroll
    for (int p = 0; p < 8; p++) {
        float4 vv[2];
        unpack_pair(acc, p, vv[0], vv[1]);
        #pragma unroll
        for (int h = 0; h < 2; h++) {
            int m = mgrp*16 + 2*p + h; int node = row0 + m;
            if (node >= Nn) continue;
            float4 lr = *(const float4*)(g_lut + LUT_NR + rs[m]*Hh + n0);
            float4 lc = *(const float4*)(g_lut + LUT_NC + cs[m]*Hh + n0);
            float4 v = vv[h];
            v.x = silu_f(v.x + lr.x + lc.x); v.y = silu_f(v.y + lr.y + lc.y);
            v.z = silu_f(v.z + lr.z + lc.z); v.w = silu_f(v.w + lr.w + lc.w);
            *(float4*)(g_U + (size_t)node*Hh + n0) = v;
        }
    }
}

// ---------------- node MLP second linear + residual + LayerNorm -> writes g_h
__global__ void __launch_bounds__(256,2)
k_n2(const float* __restrict__ n2w, const float* __restrict__ n2b,
     const float* __restrict__ lng, const float* __restrict__ lnb, int li) {
    extern __shared__ float sm[];
    float* Xs = sm;
    float* Ws = sm + 256*MP;
    __shared__ float mus[64], rss[64];
    int tid = threadIdx.x;
    int row0 = blockIdx.x * 64;
    build_rows(g_U, row0, Xs);
    unsigned long long acc[32];
    #pragma unroll
    for (int i = 0; i < 32; i++) acc[i] = 0ull;
    gemm_core(n2w + (size_t)li*Hh*Hh, Xs, Ws, acc);
    __syncthreads();                         // done reading Xs: reuse as x buffer
    float* xs = sm;                          // [64][260]
    int nthr = tid & 63, mgrp = tid >> 6, n0 = nthr*4;
    float4 bb = *(const float4*)(n2b + li*Hh + n0);
    #pragma unroll
    for (int p = 0; p < 8; p++) {
        float4 vv[2];
        unpack_pair(acc, p, vv[0], vv[1]);
        #pragma unroll
        for (int h = 0; h < 2; h++) {
            int m = mgrp*16 + 2*p + h; int node = row0 + m;
            int nc = (node > Nn-1) ? Nn-1 : node;
            float4 hv = *(const float4*)(g_h + (size_t)nc*Hh + n0);
            float4 v = vv[h];
            v.x += bb.x + hv.x; v.y += bb.y + hv.y; v.z += bb.z + hv.z; v.w += bb.w + hv.w;
            *(float4*)(xs + m*260 + n0) = v;
        }
    }
    __syncthreads();
    int lane = tid & 31, w = tid >> 5;
    for (int rrow = w*8; rrow < w*8 + 8; rrow++) {
        float s = 0.f, q = 0.f;
        #pragma unroll
        for (int j = 0; j < 8; j++) {
            float v = xs[rrow*260 + lane + j*32];
            s += v; q += v*v;
        }
        #pragma unroll
        for (int o = 16; o; o >>= 1) {
            s += __shfl_xor_sync(0xffffffffu, s, o);
            q += __shfl_xor_sync(0xffffffffu, q, o);
        }
        if (lane == 0) {
            float mu = s * (1.f/256.f);
            float var = q * (1.f/256.f) - mu*mu;
            mus[rrow] = mu;
            rss[rrow] = rsqrtf(fmaxf(var, 0.f) + 1e-5f);
        }
    }
    __syncthreads();
    for (int idx = tid; idx < 64*Hh; idx += 256) {
        int m = idx >> 8, n = idx & 255;
        int node = row0 + m;
        if (node < Nn) {
            float v = (xs[m*260 + n] - mus[m]) * rss[m] * lng[li*Hh + n] + lnb[li*Hh + n];
            g_h[(size_t)node*Hh + n] = v;
        }
    }
}

// ---------------- output projection: out = h @ out_w[256,64] + out_b
__global__ void __launch_bounds__(256,2)
k_out(const float* __restrict__ outw, const float* __restrict__ outb, float* __restrict__ out) {
    extern __shared__ float sm[];
    float* Xs = sm;
    float* Ws = sm + 256*MP;   // [KT][64]
    int tid = threadIdx.x;
    int row0 = blockIdx.x * 64;
    build_rows(g_h, row0, Xs);
    int nthr = tid & 15, mgrp = tid >> 4, n0 = nthr*4;
    float4 acc[4];
    #pragma unroll
    for (int i = 0; i < 4; i++) acc[i] = make_float4(0.f,0.f,0.f,0.f);
    const float4* Wg4 = (const float4*)outw;
    float4* Ws4 = (float4*)Ws;
    for (int kt = 0; kt < 8; kt++) {
        __syncthreads();
        Ws4[tid]       = Wg4[kt*512 + tid];
        Ws4[256 + tid] = Wg4[kt*512 + 256 + tid];
        __syncthreads();
        #pragma unroll
        for (int kk = 0; kk < KT; kk++) {
            int k = kt*KT + kk;
            float4 w = Ws4[kk*16 + nthr];
            float4 t = *(const float4*)(Xs + k*MP + mgrp*4);
            acc[0].x += t.x*w.x; acc[0].y += t.x*w.y; acc[0].z += t.x*w.z; acc[0].w += t.x*w.w;
            acc[1].x += t.y*w.x; acc[1].y += t.y*w.y; acc[1].z += t.y*w.z; acc[1].w += t.y*w.w;
            acc[2].x += t.z*w.x; acc[2].y += t.z*w.y; acc[2].z += t.z*w.z; acc[2].w += t.z*w.w;
            acc[3].x += t.w*w.x; acc[3].y += t.w*w.y; acc[3].z += t.w*w.z; acc[3].w += t.w*w.w;
        }
    }
    float4 bb = *(const float4*)(outb + n0);
    #pragma unroll
    for (int i = 0; i < 4; i++) {
        int node = row0 + mgrp*4 + i;
        if (node < Nn) {
            float4 v = acc[i];
            v.x += bb.x; v.y += bb.y; v.z += bb.z; v.w += bb.w;
            *(float4*)(out + (size_t)node*64 + n0) = v;
        }
    }
}

// ---------------- launcher ----------------
extern "C" void kernel_launch(void* const* d_in, const int* in_sizes, int n_in,
                              void* d_out, int out_size) {
    const float* scalars      = (const float*)d_in[0];
    const int*   eidx         = (const int*)  d_in[1];
    const int*   erel         = (const int*)  d_in[2];
    const int*   ncol         = (const int*)  d_in[3];
    const int*   nrole        = (const int*)  d_in[4];
    const float* blk_role_emb = (const float*)d_in[5];
    const float* blk_col_emb  = (const float*)d_in[6];
    const float* in_w         = (const float*)d_in[7];
    const float* in_b         = (const float*)d_in[8];
    const float* rel_embs     = (const float*)d_in[9];
    const float* role_embs    = (const float*)d_in[10];
    const float* col_embs     = (const float*)d_in[11];
    const float* e1_w         = (const float*)d_in[12];
    const float* e1_b         = (const float*)d_in[13];
    const float* e2_w         = (const float*)d_in[14];
    const float* e2_b         = (const float*)d_in[15];
    const float* n1_w         = (const float*)d_in[16];
    const float* n1_b         = (const float*)d_in[17];
    const float* n2_w         = (const float*)d_in[18];
    const float* n2_b         = (const float*)d_in[19];
    const float* ln_g         = (const float*)d_in[20];
    const float* ln_b         = (const float*)d_in[21];
    const float* out_w        = (const float*)d_in[22];
    const float* out_b        = (const float*)d_in[23];
    const int* esrc = eidx;
    const int* edst = eidx + Ee;

    size_t sm_gemm = (size_t)(256*MP + KT*256) * sizeof(float);  // 102400 B
    size_t sm_out  = (size_t)(256*MP + KT*64)  * sizeof(float);  // 77824 B
    cudaFuncSetAttribute(k_pq,   cudaFuncAttributeMaxDynamicSharedMemorySize, (int)sm_gemm);
    cudaFuncSetAttribute(k_edge, cudaFuncAttributeMaxDynamicSharedMemorySize, (int)sm_gemm);
    cudaFuncSetAttribute(k_n1,   cudaFuncAttributeMaxDynamicSharedMemorySize, (int)sm_gemm);
    cudaFuncSetAttribute(k_n2,   cudaFuncAttributeMaxDynamicSharedMemorySize, (int)sm_gemm);
    cudaFuncSetAttribute(k_out,  cudaFuncAttributeMaxDynamicSharedMemorySize, (int)sm_out);

    int nb = (Nn + 63) / 64;  // 782
    int zb = (int)(((size_t)Nn*Hh/4 + 255) / 256);

    k_input<<<nb, 256>>>(scalars, ncol, nrole, blk_col_emb, blk_role_emb, in_w, in_b);

    for (int li = 0; li < NLAYERS; li++) {
        k_lut<<<41, 256>>>(rel_embs, role_embs, col_embs, e1_w, e1_b, n1_w, n1_b, li);
        dim3 gpq(nb, 2);
        k_pq<<<gpq, 256, sm_gemm>>>(e1_w, nrole, ncol, li);
        k_zero<<<zb, 256>>>();
        k_edge<<<Ee/64, 256, sm_gemm>>>(esrc, edst, erel, e2_w, e2_b, li);
        k_n1<<<nb, 256, sm_gemm>>>(n1_w, nrole, ncol, li);
        k_n2<<<nb, 256, sm_gemm>>>(n2_w, n2_b, ln_g, ln_b, li);
    }
    k_out<<<nb, 256, sm_out>>>(out_w, out_b, (float*)d_out);
}